// round 16
// baseline (speedup 1.0000x reference)
#include <cuda_runtime.h>
#include <math.h>
#include <stdint.h>

// ---------------------------------------------------------------------------
// Problem constants
// ---------------------------------------------------------------------------
#define BSZ   8
#define HDIM  128
#define WDIM  128
#define CCH   192
#define LTOK  16384
#define C8    24
#define MTOT  (BSZ * LTOK)   // 131072

static __device__ __forceinline__ float gelu_erf(float x) {
    return 0.5f * x * (1.0f + erff(x * 0.70710678118654752f));
}
static __device__ __forceinline__ float sigmoidf_(float x) {
    return 1.0f / (1.0f + expf(-x));
}
static __device__ __forceinline__ uint32_t f2tf32(float x) {
    uint32_t r;
    asm("cvt.rna.tf32.f32 %0, %1;" : "=r"(r) : "f"(x));
    return r;
}

// m16n8k8 tf32 tensor-core MMA (proven layout)
static __device__ __forceinline__ void mma_tf32(
    float* c, const uint32_t* a, const uint32_t* b)
{
    asm volatile(
        "mma.sync.aligned.m16n8k8.row.col.f32.tf32.tf32.f32 "
        "{%0,%1,%2,%3}, {%4,%5,%6,%7}, {%8,%9}, {%0,%1,%2,%3};\n"
        : "+f"(c[0]), "+f"(c[1]), "+f"(c[2]), "+f"(c[3])
        : "r"(a[0]), "r"(a[1]), "r"(a[2]), "r"(a[3]),
          "r"(b[0]), "r"(b[1]));
}

// ---------------------------------------------------------------------------
// Device scratch (g_conv1 eliminated)
// ---------------------------------------------------------------------------
__device__ float g_qkv [MTOT * 3 * CCH];   // (B,L,3C)
__device__ float g_fuimg[MTOT * CCH];      // (B,C,H,W) gated attn out (NCHW)
__device__ float g_conv2[MTOT * CCH];      // (B,C,H,W)
__device__ float g_sgate[MTOT];
__device__ float g_pool [BSZ * CCH];       // SUM over H*W
__device__ float g_cgate[BSZ * CCH];

// ---------------------------------------------------------------------------
// GEMM via mma.sync tf32 — double-buffered software pipeline (R12-proven).
// MODE 0: A = x row-major (transposed in loader); out = g_qkv
// MODE 1: A = g_conv2 k-major * g_cgate; out = Cout
// ---------------------------------------------------------------------------
#define APAD 136
#define BPAD 104

template<int MODE, int NFULL>
__global__ __launch_bounds__(192) void mma_gemm_kernel(
    const float* __restrict__ Ain,
    const float* __restrict__ Bw,
    const float* __restrict__ bias,
    float* __restrict__ Cout)
{
    __shared__ uint32_t As[2][16][APAD];
    __shared__ uint32_t Bs[2][16][BPAD];

    const int tid  = threadIdx.x;
    const int wid  = tid >> 5;
    const int lane = tid & 31;
    const int gid  = lane >> 2;
    const int tig  = lane & 3;
    const int warp_m = wid & 1;
    const int warp_n = wid >> 1;

    const int n0 = blockIdx.x * 96;
    const int m0 = blockIdx.y * 128;
    const int bb = m0 / LTOK;
    const int lb = m0 % LTOK;

    float* __restrict__ outp = (MODE == 0) ? g_qkv : Cout;

    float acc[4][4][4];
#pragma unroll
    for (int mt = 0; mt < 4; mt++)
#pragma unroll
        for (int nt = 0; nt < 4; nt++)
#pragma unroll
            for (int v = 0; v < 4; v++) acc[mt][nt][v] = 0.0f;

    float4 aReg[3];
    float  gReg[3];
    float4 bReg[2];

    auto ldg_tiles = [&](int kt) {
        if (MODE == 0) {
#pragma unroll
            for (int it = 0; it < 3; it++) {
                const int lin = tid + it * 192;
                if (lin < 512) {
                    const int row = lin >> 2;
                    const int q   = (lin & 3) * 4;
                    aReg[it] = *(const float4*)(Ain + (size_t)(m0 + row) * CCH + kt + q);
                }
            }
        } else {
#pragma unroll
            for (int it = 0; it < 3; it++) {
                const int lin = tid + it * 192;
                if (lin < 512) {
                    const int k  = lin >> 5;
                    const int mq = (lin & 31) << 2;
                    aReg[it] = *(const float4*)(g_conv2 + (size_t)bb * CCH * LTOK
                                                + (size_t)(kt + k) * LTOK + lb + mq);
                    gReg[it] = g_cgate[bb * CCH + kt + k];
                }
            }
        }
#pragma unroll
        for (int it = 0; it < 2; it++) {
            const int lin = tid + it * 192;
            const int k   = lin / 24;
            const int nq  = (lin % 24) << 2;
            bReg[it] = *(const float4*)(Bw + (size_t)(kt + k) * NFULL + n0 + nq);
        }
    };

    auto sts_tiles = [&](int buf) {
        if (MODE == 0) {
#pragma unroll
            for (int it = 0; it < 3; it++) {
                const int lin = tid + it * 192;
                if (lin < 512) {
                    const int row = lin >> 2;
                    const int q   = (lin & 3) * 4;
                    As[buf][q + 0][row] = f2tf32(aReg[it].x);
                    As[buf][q + 1][row] = f2tf32(aReg[it].y);
                    As[buf][q + 2][row] = f2tf32(aReg[it].z);
                    As[buf][q + 3][row] = f2tf32(aReg[it].w);
                }
            }
        } else {
#pragma unroll
            for (int it = 0; it < 3; it++) {
                const int lin = tid + it * 192;
                if (lin < 512) {
                    const int k  = lin >> 5;
                    const int mq = (lin & 31) << 2;
                    uint4 t;
                    t.x = f2tf32(aReg[it].x * gReg[it]);
                    t.y = f2tf32(aReg[it].y * gReg[it]);
                    t.z = f2tf32(aReg[it].z * gReg[it]);
                    t.w = f2tf32(aReg[it].w * gReg[it]);
                    *(uint4*)&As[buf][k][mq] = t;
                }
            }
        }
#pragma unroll
        for (int it = 0; it < 2; it++) {
            const int lin = tid + it * 192;
            const int k   = lin / 24;
            const int nq  = (lin % 24) << 2;
            uint4 t;
            t.x = f2tf32(bReg[it].x); t.y = f2tf32(bReg[it].y);
            t.z = f2tf32(bReg[it].z); t.w = f2tf32(bReg[it].w);
            *(uint4*)&Bs[buf][k][nq] = t;
        }
    };

    auto compute = [&](int buf) {
#pragma unroll
        for (int ks = 0; ks < 2; ks++) {
            const int kr = ks * 8;
            uint32_t af[4][4];
#pragma unroll
            for (int mt = 0; mt < 4; mt++) {
                const int mr = warp_m * 64 + mt * 16;
                af[mt][0] = As[buf][kr + tig    ][mr + gid];
                af[mt][1] = As[buf][kr + tig    ][mr + gid + 8];
                af[mt][2] = As[buf][kr + tig + 4][mr + gid];
                af[mt][3] = As[buf][kr + tig + 4][mr + gid + 8];
            }
            uint32_t bf[4][2];
#pragma unroll
            for (int nt = 0; nt < 4; nt++) {
                const int nb = warp_n * 32 + nt * 8;
                bf[nt][0] = Bs[buf][kr + tig    ][nb + gid];
                bf[nt][1] = Bs[buf][kr + tig + 4][nb + gid];
            }
#pragma unroll
            for (int mt = 0; mt < 4; mt++)
#pragma unroll
                for (int nt = 0; nt < 4; nt++)
                    mma_tf32(acc[mt][nt], af[mt], bf[nt]);
        }
    };

    // prologue
    ldg_tiles(0);
    sts_tiles(0);
    __syncthreads();

    for (int t = 0; t < 12; t++) {
        const int cur = t & 1;
        if (t < 11) ldg_tiles((t + 1) * 16);
        compute(cur);
        if (t < 11) sts_tiles(cur ^ 1);
        __syncthreads();
    }

#pragma unroll
    for (int mt = 0; mt < 4; mt++) {
        const int r0 = m0 + warp_m * 64 + mt * 16 + gid;
#pragma unroll
        for (int nt = 0; nt < 4; nt++) {
            const int col = n0 + warp_n * 32 + nt * 8 + tig * 2;
            const float bx = bias[col], by = bias[col + 1];
            float2 v0 = { acc[mt][nt][0] + bx, acc[mt][nt][1] + by };
            float2 v1 = { acc[mt][nt][2] + bx, acc[mt][nt][3] + by };
            *(float2*)(outp + (size_t)r0 * NFULL + col) = v0;
            *(float2*)(outp + (size_t)(r0 + 8) * NFULL + col) = v1;
        }
    }
}

// ---------------------------------------------------------------------------
// Windowed attention body — proven; both variants in one grid.
// ---------------------------------------------------------------------------
#define ATT_SMEM 102912
#define ATT_BLOCKS (BSZ * (HDIM / 8) * (WDIM / 16) * 3)   // 3072 per variant

template<int HS, int WS, int COFF>
static __device__ __forceinline__ void attn_body(int bid)
{
    extern __shared__ char sm[];
    float*    Ssm  = (float*)sm;                    // [128][132]
    uint32_t* Su   = (uint32_t*)sm;
    float*    rsum = (float*)(sm + 67584);
    uint32_t* Qs   = (uint32_t*)(sm + 68096);       // [32][136]
    uint32_t* Ks   = Qs + 32 * 136;
    uint32_t* Vs   = (uint32_t*)(sm + 68096);       // [128][40]
    float*    Os   = (float*)(sm + 68096);          // [128][33]

    constexpr int WWn = WDIM / WS;
    constexpr int WH  = HDIM / HS;
    constexpr float SCALE3 = 3.0f * 0.17677669529663688f;   // 3/sqrt(32)

    const int head = bid % 3; bid /= 3;
    const int ww = bid % WWn; bid /= WWn;
    const int wh = bid % WH;  bid /= WH;
    const int b  = bid;
    const int co = COFF + head * 32;

    const int t    = threadIdx.x;
    const int wid  = t >> 5;
    const int lane = t & 31;
    const int gid  = lane >> 2;
    const int tig  = lane & 3;

    const int sL = t >> 2;
    const int d0 = (t & 3) * 8;

    // ---- Phase 0: Q,K -> smem [dim][token] tf32 ----
#pragma unroll
    for (int p = 0; p < 2; p++) {
        const int ts = p * 64 + sL;
        const int l  = (wh * HS + ts / WS) * WDIM + ww * WS + ts % WS;
        const float* qb = g_qkv + ((size_t)b * LTOK + l) * (3 * CCH) + co;
        const float* kb = qb + CCH;
        const float4 q0 = *(const float4*)(qb + d0);
        const float4 q1 = *(const float4*)(qb + d0 + 4);
        const float4 k0 = *(const float4*)(kb + d0);
        const float4 k1 = *(const float4*)(kb + d0 + 4);
        const float qa[8] = {q0.x,q0.y,q0.z,q0.w,q1.x,q1.y,q1.z,q1.w};
        const float ka[8] = {k0.x,k0.y,k0.z,k0.w,k1.x,k1.y,k1.z,k1.w};
#pragma unroll
        for (int j = 0; j < 8; j++) {
            Qs[(d0 + j) * 136 + ts] = f2tf32(qa[j]);
            Ks[(d0 + j) * 136 + ts] = f2tf32(ka[j]);
        }
    }
    __syncthreads();

    // ---- Phase 1: S rows wid*16..+15 ----
    {
        const int mrb = wid * 16;
#pragma unroll
        for (int nc = 0; nc < 4; nc++) {
            float acc[4][4] = {};
#pragma unroll
            for (int ks = 0; ks < 4; ks++) {
                const int kr = ks * 8;
                uint32_t af[4];
                af[0] = Qs[(kr + tig    ) * 136 + mrb + gid];
                af[1] = Qs[(kr + tig    ) * 136 + mrb + gid + 8];
                af[2] = Qs[(kr + tig + 4) * 136 + mrb + gid];
                af[3] = Qs[(kr + tig + 4) * 136 + mrb + gid + 8];
                uint32_t bf[4][2];
#pragma unroll
                for (int nt = 0; nt < 4; nt++) {
                    const int nb = nc * 32 + nt * 8;
                    bf[nt][0] = Ks[(kr + tig    ) * 136 + nb + gid];
                    bf[nt][1] = Ks[(kr + tig + 4) * 136 + nb + gid];
                }
#pragma unroll
                for (int nt = 0; nt < 4; nt++)
                    mma_tf32(acc[nt], af, bf[nt]);
            }
            const int r0 = mrb + gid;
#pragma unroll
            for (int nt = 0; nt < 4; nt++) {
                const int col = nc * 32 + nt * 8 + tig * 2;
                Ssm[r0 * 132 + col]           = acc[nt][0] * SCALE3;
                Ssm[r0 * 132 + col + 1]       = acc[nt][1] * SCALE3;
                Ssm[(r0 + 8) * 132 + col]     = acc[nt][2] * SCALE3;
                Ssm[(r0 + 8) * 132 + col + 1] = acc[nt][3] * SCALE3;
            }
        }
    }
    __syncthreads();

    // ---- Phase 2a: V -> X region ----
#pragma unroll
    for (int p = 0; p < 2; p++) {
        const int ts = p * 64 + sL;
        const int l  = (wh * HS + ts / WS) * WDIM + ww * WS + ts % WS;
        const float* vb = g_qkv + ((size_t)b * LTOK + l) * (3 * CCH) + 2 * CCH + co;
        const float4 v0 = *(const float4*)(vb + d0);
        const float4 v1 = *(const float4*)(vb + d0 + 4);
        uint4 t0, t1;
        t0.x = f2tf32(v0.x); t0.y = f2tf32(v0.y); t0.z = f2tf32(v0.z); t0.w = f2tf32(v0.w);
        t1.x = f2tf32(v1.x); t1.y = f2tf32(v1.y); t1.z = f2tf32(v1.z); t1.w = f2tf32(v1.w);
        *(uint4*)(Vs + ts * 40 + d0)     = t0;
        *(uint4*)(Vs + ts * 40 + d0 + 4) = t1;
    }

    // ---- Phase 2b: quad-per-row softmax (gate folded) ----
#pragma unroll
    for (int i = 0; i < 2; i++) {
        const int r = wid * 16 + i * 8 + gid;
        float v[32];
#pragma unroll
        for (int jj = 0; jj < 32; jj++) v[jj] = Ssm[r * 132 + tig + 4 * jj];
        float mx = v[0];
#pragma unroll
        for (int jj = 1; jj < 32; jj++) mx = fmaxf(mx, v[jj]);
        mx = fmaxf(mx, __shfl_xor_sync(~0u, mx, 1));
        mx = fmaxf(mx, __shfl_xor_sync(~0u, mx, 2));
        float s = 0.0f;
#pragma unroll
        for (int jj = 0; jj < 32; jj++) {
            const float e = __expf(v[jj] - mx);
            s += e;
            Su[r * 132 + tig + 4 * jj] = f2tf32(e);
        }
        s += __shfl_xor_sync(~0u, s, 1);
        s += __shfl_xor_sync(~0u, s, 2);
        if (tig == 0) {
            const int lr = (wh * HS + r / WS) * WDIM + ww * WS + r % WS;
            rsum[r] = 3.0f * g_sgate[b * LTOK + lr] / s;
        }
    }
    __syncthreads();

    // ---- Phase 3: O^T = V^T P^T ----
    {
        const int nbb = wid * 16;
        float acc[2][2][4] = {};
#pragma unroll
        for (int ks = 0; ks < 16; ks++) {
            const int kr = ks * 8;
            uint32_t af[2][4];
#pragma unroll
            for (int mt = 0; mt < 2; mt++) {
                const int mr = mt * 16;
                af[mt][0] = Vs[(kr + tig    ) * 40 + mr + gid];
                af[mt][1] = Vs[(kr + tig    ) * 40 + mr + gid + 8];
                af[mt][2] = Vs[(kr + tig + 4) * 40 + mr + gid];
                af[mt][3] = Vs[(kr + tig + 4) * 40 + mr + gid + 8];
            }
            uint32_t bf[2][2];
#pragma unroll
            for (int nt = 0; nt < 2; nt++) {
                const int nb = nbb + nt * 8;
                bf[nt][0] = Su[(nb + gid) * 132 + kr + tig];
                bf[nt][1] = Su[(nb + gid) * 132 + kr + tig + 4];
            }
#pragma unroll
            for (int mt = 0; mt < 2; mt++)
#pragma unroll
                for (int nt = 0; nt < 2; nt++)
                    mma_tf32(acc[mt][nt], af[mt], bf[nt]);
        }
        __syncthreads();

#pragma unroll
        for (int mt = 0; mt < 2; mt++) {
            const int dim0 = mt * 16 + gid;
#pragma unroll
            for (int nt = 0; nt < 2; nt++) {
                const int r = nbb + nt * 8 + tig * 2;
                const float s0 = rsum[r], s1 = rsum[r + 1];
                Os[r * 33 + dim0]           = acc[mt][nt][0] * s0;
                Os[(r + 1) * 33 + dim0]     = acc[mt][nt][1] * s1;
                Os[r * 33 + dim0 + 8]       = acc[mt][nt][2] * s0;
                Os[(r + 1) * 33 + dim0 + 8] = acc[mt][nt][3] * s1;
            }
        }
    }
    __syncthreads();

    // ---- Phase 4: transposed NCHW writeout ----
#pragma unroll
    for (int cc = 0; cc < 4; cc++) {
        const int c = wid * 4 + cc;
        float* cbase = g_fuimg + ((size_t)b * CCH + co + c) * LTOK;
#pragma unroll
        for (int rp = 0; rp < 4; rp++) {
            const int ts = rp * 32 + lane;
            const int l  = (wh * HS + ts / WS) * WDIM + ww * WS + ts % WS;
            cbase[l] = Os[ts * 33 + c];
        }
    }
}

__global__ __launch_bounds__(256) void attn_both_kernel()
{
    const int bid = blockIdx.x;
    if (bid < ATT_BLOCKS) attn_body<8, 16, 0>(bid);
    else                  attn_body<16, 8, 96>(bid - ATT_BLOCKS);
}

// ---------------------------------------------------------------------------
// zero g_pool
// ---------------------------------------------------------------------------
__global__ void zero_pool_kernel()
{
    const int i = blockIdx.x * 256 + threadIdx.x;
    if (i < BSZ * CCH) g_pool[i] = 0.0f;
}

// ---------------------------------------------------------------------------
// FUSED conv1 + BN + GELU + pool + spatial-interaction -> g_sgate, g_pool.
// Block = one image row (b,h), thread = one pixel. g_conv1 never materialized.
// Conv + spatial fmaf chains bit-identical to the proven separate kernels.
// ---------------------------------------------------------------------------
__global__ __launch_bounds__(128) void conv1_spatial_kernel(
    const float* __restrict__ x,
    const float* __restrict__ w_dw1, const float* __restrict__ b_dw1,
    const float* __restrict__ gbn1,  const float* __restrict__ bebn1,
    const float* __restrict__ w_si1, const float* __restrict__ b_si1,
    const float* __restrict__ g_si,  const float* __restrict__ be_si,
    const float* __restrict__ w_si2, const float* __restrict__ b_si2)
{
    __shared__ float wsm[CCH * C8];   // [c][o]
    for (int i = threadIdx.x; i < CCH * C8; i += 128)
        wsm[i] = w_si1[(i % C8) * CCH + (i / C8)];
    __syncthreads();

    const int bh = blockIdx.x;          // b*128 + h
    const int b  = bh >> 7;
    const int h  = bh & 127;
    const int px = threadIdx.x;         // 0..127 (= w; full row, so px edges are image edges)
    const int lane = px & 31;

    const float bni = rsqrtf(1.0f + 1e-5f);

    float t[C8];
#pragma unroll
    for (int o = 0; o < C8; o++) t[o] = 0.0f;

    for (int c = 0; c < CCH; c++) {
        const float* base = x + ((size_t)(b * CCH + c)) * LTOK;
        float wk[9];
#pragma unroll
        for (int i = 0; i < 9; i++) wk[i] = w_dw1[c * 9 + i];   // warp-uniform

        float acc = 0.0f;
#pragma unroll
        for (int r = 0; r < 3; r++) {
            const int hh = h - 1 + r;                 // block-uniform predicate
            if (hh < 0 || hh >= HDIM) continue;
            const float* row = base + hh * WDIM;
            const float vm = row[px];
            float lf = __shfl_up_sync(0xffffffffu, vm, 1);
            if (lane == 0)  lf = (px == 0)   ? 0.0f : row[px - 1];
            float rt = __shfl_down_sync(0xffffffffu, vm, 1);
            if (lane == 31) rt = (px == 127) ? 0.0f : row[px + 1];
            acc = fmaf(wk[r*3+0], lf, fmaf(wk[r*3+1], vm, fmaf(wk[r*3+2], rt, acc)));
        }
        const float val = gelu_erf((acc + b_dw1[c]) * (gbn1[c] * bni) + bebn1[c]);

        // pool (warp partial sum -> global RED)
        float ws = val;
#pragma unroll
        for (int off = 16; off > 0; off >>= 1)
            ws += __shfl_xor_sync(0xffffffffu, ws, off);
        if (lane == 0) atomicAdd(&g_pool[b * CCH + c], ws);

        // spatial accumulation (proven order)
        const float4* wr = (const float4*)&wsm[c * C8];
#pragma unroll
        for (int o4 = 0; o4 < 6; o4++) {
            const float4 w = wr[o4];
            t[o4*4+0] = fmaf(w.x, val, t[o4*4+0]);
            t[o4*4+1] = fmaf(w.y, val, t[o4*4+1]);
            t[o4*4+2] = fmaf(w.z, val, t[o4*4+2]);
            t[o4*4+3] = fmaf(w.w, val, t[o4*4+3]);
        }
    }

    float s = b_si2[0];
#pragma unroll
    for (int o = 0; o < C8; o++) {
        const float u = (t[o] + b_si1[o]) * (g_si[o] * bni) + be_si[o];
        s = fmaf(w_si2[o], gelu_erf(u), s);
    }
    g_sgate[b * LTOK + h * WDIM + px] = 1.0f + sigmoidf_(s);
}

// ---------------------------------------------------------------------------
// Depthwise 3x3 + bias + BN + GELU for attention output (conv2), 4 px/thread.
// ---------------------------------------------------------------------------
__global__ __launch_bounds__(256) void dwconv2_kernel(
    const float* __restrict__ wdw,
    const float* __restrict__ bdw,
    const float* __restrict__ gbn,
    const float* __restrict__ bebn)
{
    const int idx = blockIdx.x * 256 + threadIdx.x;
    const int w0 = (idx & 31) * 4;
    const int h  = (idx >> 5) & 127;
    const int bc = idx >> 12;
    const int c  = bc % CCH;

    const float* p = g_fuimg + (size_t)bc * LTOK;
    float wk[9];
#pragma unroll
    for (int i = 0; i < 9; i++) wk[i] = wdw[c * 9 + i];

    float o0 = 0.f, o1 = 0.f, o2 = 0.f, o3 = 0.f;
#pragma unroll
    for (int r = 0; r < 3; r++) {
        const int hh = h - 1 + r;
        if (hh < 0 || hh >= HDIM) continue;
        const float* row = p + hh * WDIM;
        const float4 cc = *(const float4*)(row + w0);
        const float lf = (w0 > 0)   ? row[w0 - 1] : 0.0f;
        const float rt = (w0 < 124) ? row[w0 + 4] : 0.0f;
        const float k0 = wk[r*3+0], k1 = wk[r*3+1], k2 = wk[r*3+2];
        o0 = fmaf(k0, lf,   fmaf(k1, cc.x, fmaf(k2, cc.y, o0)));
        o1 = fmaf(k0, cc.x, fmaf(k1, cc.y, fmaf(k2, cc.z, o1)));
        o2 = fmaf(k0, cc.y, fmaf(k1, cc.z, fmaf(k2, cc.w, o2)));
        o3 = fmaf(k0, cc.z, fmaf(k1, cc.w, fmaf(k2, rt,   o3)));
    }
    const float bni = rsqrtf(1.0f + 1e-5f);
    const float sc = gbn[c] * bni, bb = bebn[c], bs = bdw[c];
    float4 o;
    o.x = gelu_erf((o0 + bs) * sc + bb);
    o.y = gelu_erf((o1 + bs) * sc + bb);
    o.z = gelu_erf((o2 + bs) * sc + bb);
    o.w = gelu_erf((o3 + bs) * sc + bb);
    *(float4*)(g_conv2 + (size_t)idx * 4) = o;
}

// ---------------------------------------------------------------------------
// Channel interaction -> g_cgate (g_pool holds SUM; scale by 1/LTOK)
// ---------------------------------------------------------------------------
__global__ __launch_bounds__(192) void channel_kernel(
    const float* __restrict__ w_ci1, const float* __restrict__ b_ci1,
    const float* __restrict__ g_ci,  const float* __restrict__ be_ci,
    const float* __restrict__ w_ci2, const float* __restrict__ b_ci2)
{
    const int b = blockIdx.x;
    __shared__ float t[C8];
    const float bni = rsqrtf(1.0f + 1e-5f);
    const float inv = 1.0f / LTOK;
    if (threadIdx.x < C8) {
        const int o = threadIdx.x;
        float s = b_ci1[o];
        for (int c = 0; c < CCH; c++)
            s = fmaf(w_ci1[o * CCH + c], g_pool[b * CCH + c] * inv, s);
        s = s * (g_ci[o] * bni) + be_ci[o];
        t[o] = gelu_erf(s);
    }
    __syncthreads();
    const int c = threadIdx.x;
    float s = b_ci2[c];
#pragma unroll
    for (int o = 0; o < C8; o++) s = fmaf(w_ci2[c * C8 + o], t[o], s);
    g_cgate[b * CCH + c] = 1.0f + sigmoidf_(s);
}

// ---------------------------------------------------------------------------
// kernel_launch (single stream; fork removed — proven neutral)
// ---------------------------------------------------------------------------
extern "C" void kernel_launch(void* const* d_in, const int* in_sizes, int n_in,
                              void* d_out, int out_size)
{
    const float* x      = (const float*)d_in[0];
    const float* w_qkv  = (const float*)d_in[1];
    const float* b_qkv  = (const float*)d_in[2];
    const float* w_dw1  = (const float*)d_in[3];
    const float* b_dw1  = (const float*)d_in[4];
    const float* gbn1   = (const float*)d_in[5];
    const float* bebn1  = (const float*)d_in[6];
    const float* w_si1  = (const float*)d_in[7];
    const float* b_si1  = (const float*)d_in[8];
    const float* g_si   = (const float*)d_in[9];
    const float* be_si  = (const float*)d_in[10];
    const float* w_si2  = (const float*)d_in[11];
    const float* b_si2  = (const float*)d_in[12];
    const float* w_ci1  = (const float*)d_in[13];
    const float* b_ci1  = (const float*)d_in[14];
    const float* g_ci   = (const float*)d_in[15];
    const float* be_ci  = (const float*)d_in[16];
    const float* w_ci2  = (const float*)d_in[17];
    const float* b_ci2  = (const float*)d_in[18];
    const float* w_dw2  = (const float*)d_in[19];
    const float* b_dw2  = (const float*)d_in[20];
    const float* gbn2   = (const float*)d_in[21];
    const float* bebn2  = (const float*)d_in[22];
    const float* w_proj = (const float*)d_in[23];
    const float* b_proj = (const float*)d_in[24];
    float* out = (float*)d_out;

    cudaFuncSetAttribute(attn_both_kernel,
                         cudaFuncAttributeMaxDynamicSharedMemorySize, ATT_SMEM);

    // 0) qkv = x @ w_qkv + b_qkv  (double-buffered)
    mma_gemm_kernel<0, 3 * CCH><<<dim3((3 * CCH) / 96, MTOT / 128), 192>>>(
        x, w_qkv, b_qkv, nullptr);

    // 1) fused conv1+pool+spatial -> g_sgate, g_pool  (g_conv1 eliminated)
    zero_pool_kernel<<<(BSZ * CCH + 255) / 256, 256>>>();
    conv1_spatial_kernel<<<BSZ * HDIM, 128>>>(
        x, w_dw1, b_dw1, gbn1, bebn1,
        w_si1, b_si1, g_si, be_si, w_si2, b_si2);
    channel_kernel<<<BSZ, CCH>>>(w_ci1, b_ci1, g_ci, be_ci, w_ci2, b_ci2);

    // 2) attention — both variants (gate + transpose fused) -> g_fuimg
    attn_both_kernel<<<2 * ATT_BLOCKS, 256, ATT_SMEM>>>();

    // 3) conv2 -> g_conv2
    dwconv2_kernel<<<(MTOT * CCH) / 1024, 256>>>(w_dw2, b_dw2, gbn2, bebn2);

    // 4) out = (channel-gated conv2) @ w_proj + b_proj  (double-buffered)
    mma_gemm_kernel<1, CCH><<<dim3(CCH / 96, MTOT / 128), 192>>>(
        nullptr, w_proj, b_proj, out);
}

// round 17
// speedup vs baseline: 1.1754x; 1.1754x over previous
#include <cuda_runtime.h>
#include <cuda_fp16.h>
#include <math.h>
#include <stdint.h>

// ---------------------------------------------------------------------------
// Problem constants
// ---------------------------------------------------------------------------
#define BSZ   8
#define HDIM  128
#define WDIM  128
#define CCH   192
#define LTOK  16384
#define C8    24
#define MTOT  (BSZ * LTOK)   // 131072

static __device__ __forceinline__ float gelu_erf(float x) {
    return 0.5f * x * (1.0f + erff(x * 0.70710678118654752f));
}
static __device__ __forceinline__ float sigmoidf_(float x) {
    return 1.0f / (1.0f + expf(-x));
}
static __device__ __forceinline__ uint32_t f2tf32(float x) {
    uint32_t r;
    asm("cvt.rna.tf32.f32 %0, %1;" : "=r"(r) : "f"(x));
    return r;
}

// m16n8k8 tf32 tensor-core MMA (proven layout)
static __device__ __forceinline__ void mma_tf32(
    float* c, const uint32_t* a, const uint32_t* b)
{
    asm volatile(
        "mma.sync.aligned.m16n8k8.row.col.f32.tf32.tf32.f32 "
        "{%0,%1,%2,%3}, {%4,%5,%6,%7}, {%8,%9}, {%0,%1,%2,%3};\n"
        : "+f"(c[0]), "+f"(c[1]), "+f"(c[2]), "+f"(c[3])
        : "r"(a[0]), "r"(a[1]), "r"(a[2]), "r"(a[3]),
          "r"(b[0]), "r"(b[1]));
}

// ---------------------------------------------------------------------------
// Device scratch (g_qkv now fp16: halves its 600 MB round-trip)
// ---------------------------------------------------------------------------
__device__ __half g_qkvh[MTOT * 3 * CCH];  // (B,L,3C) fp16
__device__ float g_conv1[MTOT * CCH];      // (B,C,H,W)
__device__ float g_fuimg[MTOT * CCH];      // (B,C,H,W) gated attn out (NCHW)
__device__ float g_conv2[MTOT * CCH];      // (B,C,H,W)
__device__ float g_sgate[MTOT];
__device__ float g_pool [BSZ * CCH];       // SUM over H*W
__device__ float g_cgate[BSZ * CCH];

// ---------------------------------------------------------------------------
// GEMM via mma.sync tf32 — double-buffered software pipeline (R12-proven).
// MODE 0: A = x row-major (transposed in loader); out = g_qkvh (fp16)
// MODE 1: A = g_conv2 k-major * g_cgate; out = Cout (fp32)
// ---------------------------------------------------------------------------
#define APAD 136
#define BPAD 104

template<int MODE, int NFULL>
__global__ __launch_bounds__(192) void mma_gemm_kernel(
    const float* __restrict__ Ain,
    const float* __restrict__ Bw,
    const float* __restrict__ bias,
    float* __restrict__ Cout)
{
    __shared__ uint32_t As[2][16][APAD];
    __shared__ uint32_t Bs[2][16][BPAD];

    const int tid  = threadIdx.x;
    const int wid  = tid >> 5;
    const int lane = tid & 31;
    const int gid  = lane >> 2;
    const int tig  = lane & 3;
    const int warp_m = wid & 1;
    const int warp_n = wid >> 1;

    const int n0 = blockIdx.x * 96;
    const int m0 = blockIdx.y * 128;
    const int bb = m0 / LTOK;
    const int lb = m0 % LTOK;

    float acc[4][4][4];
#pragma unroll
    for (int mt = 0; mt < 4; mt++)
#pragma unroll
        for (int nt = 0; nt < 4; nt++)
#pragma unroll
            for (int v = 0; v < 4; v++) acc[mt][nt][v] = 0.0f;

    float4 aReg[3];
    float  gReg[3];
    float4 bReg[2];

    auto ldg_tiles = [&](int kt) {
        if (MODE == 0) {
#pragma unroll
            for (int it = 0; it < 3; it++) {
                const int lin = tid + it * 192;
                if (lin < 512) {
                    const int row = lin >> 2;
                    const int q   = (lin & 3) * 4;
                    aReg[it] = *(const float4*)(Ain + (size_t)(m0 + row) * CCH + kt + q);
                }
            }
        } else {
#pragma unroll
            for (int it = 0; it < 3; it++) {
                const int lin = tid + it * 192;
                if (lin < 512) {
                    const int k  = lin >> 5;
                    const int mq = (lin & 31) << 2;
                    aReg[it] = *(const float4*)(g_conv2 + (size_t)bb * CCH * LTOK
                                                + (size_t)(kt + k) * LTOK + lb + mq);
                    gReg[it] = g_cgate[bb * CCH + kt + k];
                }
            }
        }
#pragma unroll
        for (int it = 0; it < 2; it++) {
            const int lin = tid + it * 192;
            const int k   = lin / 24;
            const int nq  = (lin % 24) << 2;
            bReg[it] = *(const float4*)(Bw + (size_t)(kt + k) * NFULL + n0 + nq);
        }
    };

    auto sts_tiles = [&](int buf) {
        if (MODE == 0) {
#pragma unroll
            for (int it = 0; it < 3; it++) {
                const int lin = tid + it * 192;
                if (lin < 512) {
                    const int row = lin >> 2;
                    const int q   = (lin & 3) * 4;
                    As[buf][q + 0][row] = f2tf32(aReg[it].x);
                    As[buf][q + 1][row] = f2tf32(aReg[it].y);
                    As[buf][q + 2][row] = f2tf32(aReg[it].z);
                    As[buf][q + 3][row] = f2tf32(aReg[it].w);
                }
            }
        } else {
#pragma unroll
            for (int it = 0; it < 3; it++) {
                const int lin = tid + it * 192;
                if (lin < 512) {
                    const int k  = lin >> 5;
                    const int mq = (lin & 31) << 2;
                    uint4 t;
                    t.x = f2tf32(aReg[it].x * gReg[it]);
                    t.y = f2tf32(aReg[it].y * gReg[it]);
                    t.z = f2tf32(aReg[it].z * gReg[it]);
                    t.w = f2tf32(aReg[it].w * gReg[it]);
                    *(uint4*)&As[buf][k][mq] = t;
                }
            }
        }
#pragma unroll
        for (int it = 0; it < 2; it++) {
            const int lin = tid + it * 192;
            const int k   = lin / 24;
            const int nq  = (lin % 24) << 2;
            uint4 t;
            t.x = f2tf32(bReg[it].x); t.y = f2tf32(bReg[it].y);
            t.z = f2tf32(bReg[it].z); t.w = f2tf32(bReg[it].w);
            *(uint4*)&Bs[buf][k][nq] = t;
        }
    };

    auto compute = [&](int buf) {
#pragma unroll
        for (int ks = 0; ks < 2; ks++) {
            const int kr = ks * 8;
            uint32_t af[4][4];
#pragma unroll
            for (int mt = 0; mt < 4; mt++) {
                const int mr = warp_m * 64 + mt * 16;
                af[mt][0] = As[buf][kr + tig    ][mr + gid];
                af[mt][1] = As[buf][kr + tig    ][mr + gid + 8];
                af[mt][2] = As[buf][kr + tig + 4][mr + gid];
                af[mt][3] = As[buf][kr + tig + 4][mr + gid + 8];
            }
            uint32_t bf[4][2];
#pragma unroll
            for (int nt = 0; nt < 4; nt++) {
                const int nb = warp_n * 32 + nt * 8;
                bf[nt][0] = Bs[buf][kr + tig    ][nb + gid];
                bf[nt][1] = Bs[buf][kr + tig + 4][nb + gid];
            }
#pragma unroll
            for (int mt = 0; mt < 4; mt++)
#pragma unroll
                for (int nt = 0; nt < 4; nt++)
                    mma_tf32(acc[mt][nt], af[mt], bf[nt]);
        }
    };

    // prologue
    ldg_tiles(0);
    sts_tiles(0);
    __syncthreads();

    for (int t = 0; t < 12; t++) {
        const int cur = t & 1;
        if (t < 11) ldg_tiles((t + 1) * 16);
        compute(cur);
        if (t < 11) sts_tiles(cur ^ 1);
        __syncthreads();
    }

#pragma unroll
    for (int mt = 0; mt < 4; mt++) {
        const int r0 = m0 + warp_m * 64 + mt * 16 + gid;
#pragma unroll
        for (int nt = 0; nt < 4; nt++) {
            const int col = n0 + warp_n * 32 + nt * 8 + tig * 2;
            const float bx = bias[col], by = bias[col + 1];
            if (MODE == 0) {
                __half2 h0 = __floats2half2_rn(acc[mt][nt][0] + bx, acc[mt][nt][1] + by);
                __half2 h1 = __floats2half2_rn(acc[mt][nt][2] + bx, acc[mt][nt][3] + by);
                *(__half2*)(g_qkvh + (size_t)r0 * NFULL + col) = h0;
                *(__half2*)(g_qkvh + (size_t)(r0 + 8) * NFULL + col) = h1;
            } else {
                float2 v0 = { acc[mt][nt][0] + bx, acc[mt][nt][1] + by };
                float2 v1 = { acc[mt][nt][2] + bx, acc[mt][nt][3] + by };
                *(float2*)(Cout + (size_t)r0 * NFULL + col) = v0;
                *(float2*)(Cout + (size_t)(r0 + 8) * NFULL + col) = v1;
            }
        }
    }
}

// ---------------------------------------------------------------------------
// Windowed attention body — proven; both variants in one grid.
// q/k/v read from fp16 g_qkvh (uint4 = 8 halves), converted half->f32->tf32.
// ---------------------------------------------------------------------------
#define ATT_SMEM 102912
#define ATT_BLOCKS (BSZ * (HDIM / 8) * (WDIM / 16) * 3)   // 3072 per variant

template<int HS, int WS, int COFF>
static __device__ __forceinline__ void attn_body(int bid)
{
    extern __shared__ char sm[];
    float*    Ssm  = (float*)sm;                    // [128][132]
    uint32_t* Su   = (uint32_t*)sm;
    float*    rsum = (float*)(sm + 67584);
    uint32_t* Qs   = (uint32_t*)(sm + 68096);       // [32][136]
    uint32_t* Ks   = Qs + 32 * 136;
    uint32_t* Vs   = (uint32_t*)(sm + 68096);       // [128][40]
    float*    Os   = (float*)(sm + 68096);          // [128][33]

    constexpr int WWn = WDIM / WS;
    constexpr int WH  = HDIM / HS;
    constexpr float SCALE3 = 3.0f * 0.17677669529663688f;   // 3/sqrt(32)

    const int head = bid % 3; bid /= 3;
    const int ww = bid % WWn; bid /= WWn;
    const int wh = bid % WH;  bid /= WH;
    const int b  = bid;
    const int co = COFF + head * 32;

    const int t    = threadIdx.x;
    const int wid  = t >> 5;
    const int lane = t & 31;
    const int gid  = lane >> 2;
    const int tig  = lane & 3;

    const int sL = t >> 2;
    const int d0 = (t & 3) * 8;

    // ---- Phase 0: Q,K -> smem [dim][token] tf32 (from fp16) ----
#pragma unroll
    for (int p = 0; p < 2; p++) {
        const int ts = p * 64 + sL;
        const int l  = (wh * HS + ts / WS) * WDIM + ww * WS + ts % WS;
        const __half* qb = g_qkvh + ((size_t)b * LTOK + l) * (3 * CCH) + co;
        const __half* kb = qb + CCH;
        uint4 qu = *(const uint4*)(qb + d0);     // 8 halves
        uint4 ku = *(const uint4*)(kb + d0);
        const __half2* qh = (const __half2*)&qu;
        const __half2* kh = (const __half2*)&ku;
#pragma unroll
        for (int j = 0; j < 4; j++) {
            const float2 qf = __half22float2(qh[j]);
            const float2 kf = __half22float2(kh[j]);
            Qs[(d0 + 2*j    ) * 136 + ts] = f2tf32(qf.x);
            Qs[(d0 + 2*j + 1) * 136 + ts] = f2tf32(qf.y);
            Ks[(d0 + 2*j    ) * 136 + ts] = f2tf32(kf.x);
            Ks[(d0 + 2*j + 1) * 136 + ts] = f2tf32(kf.y);
        }
    }
    __syncthreads();

    // ---- Phase 1: S rows wid*16..+15 ----
    {
        const int mrb = wid * 16;
#pragma unroll
        for (int nc = 0; nc < 4; nc++) {
            float acc[4][4] = {};
#pragma unroll
            for (int ks = 0; ks < 4; ks++) {
                const int kr = ks * 8;
                uint32_t af[4];
                af[0] = Qs[(kr + tig    ) * 136 + mrb + gid];
                af[1] = Qs[(kr + tig    ) * 136 + mrb + gid + 8];
                af[2] = Qs[(kr + tig + 4) * 136 + mrb + gid];
                af[3] = Qs[(kr + tig + 4) * 136 + mrb + gid + 8];
                uint32_t bf[4][2];
#pragma unroll
                for (int nt = 0; nt < 4; nt++) {
                    const int nb = nc * 32 + nt * 8;
                    bf[nt][0] = Ks[(kr + tig    ) * 136 + nb + gid];
                    bf[nt][1] = Ks[(kr + tig + 4) * 136 + nb + gid];
                }
#pragma unroll
                for (int nt = 0; nt < 4; nt++)
                    mma_tf32(acc[nt], af, bf[nt]);
            }
            const int r0 = mrb + gid;
#pragma unroll
            for (int nt = 0; nt < 4; nt++) {
                const int col = nc * 32 + nt * 8 + tig * 2;
                Ssm[r0 * 132 + col]           = acc[nt][0] * SCALE3;
                Ssm[r0 * 132 + col + 1]       = acc[nt][1] * SCALE3;
                Ssm[(r0 + 8) * 132 + col]     = acc[nt][2] * SCALE3;
                Ssm[(r0 + 8) * 132 + col + 1] = acc[nt][3] * SCALE3;
            }
        }
    }
    __syncthreads();

    // ---- Phase 2a: V -> X region (from fp16) ----
#pragma unroll
    for (int p = 0; p < 2; p++) {
        const int ts = p * 64 + sL;
        const int l  = (wh * HS + ts / WS) * WDIM + ww * WS + ts % WS;
        const __half* vb = g_qkvh + ((size_t)b * LTOK + l) * (3 * CCH) + 2 * CCH + co;
        uint4 vu = *(const uint4*)(vb + d0);
        const __half2* vh = (const __half2*)&vu;
        uint4 t0, t1;
        const float2 f0 = __half22float2(vh[0]);
        const float2 f1 = __half22float2(vh[1]);
        const float2 f2 = __half22float2(vh[2]);
        const float2 f3 = __half22float2(vh[3]);
        t0.x = f2tf32(f0.x); t0.y = f2tf32(f0.y); t0.z = f2tf32(f1.x); t0.w = f2tf32(f1.y);
        t1.x = f2tf32(f2.x); t1.y = f2tf32(f2.y); t1.z = f2tf32(f3.x); t1.w = f2tf32(f3.y);
        *(uint4*)(Vs + ts * 40 + d0)     = t0;
        *(uint4*)(Vs + ts * 40 + d0 + 4) = t1;
    }

    // ---- Phase 2b: quad-per-row softmax (gate folded) ----
#pragma unroll
    for (int i = 0; i < 2; i++) {
        const int r = wid * 16 + i * 8 + gid;
        float v[32];
#pragma unroll
        for (int jj = 0; jj < 32; jj++) v[jj] = Ssm[r * 132 + tig + 4 * jj];
        float mx = v[0];
#pragma unroll
        for (int jj = 1; jj < 32; jj++) mx = fmaxf(mx, v[jj]);
        mx = fmaxf(mx, __shfl_xor_sync(~0u, mx, 1));
        mx = fmaxf(mx, __shfl_xor_sync(~0u, mx, 2));
        float s = 0.0f;
#pragma unroll
        for (int jj = 0; jj < 32; jj++) {
            const float e = __expf(v[jj] - mx);
            s += e;
            Su[r * 132 + tig + 4 * jj] = f2tf32(e);
        }
        s += __shfl_xor_sync(~0u, s, 1);
        s += __shfl_xor_sync(~0u, s, 2);
        if (tig == 0) {
            const int lr = (wh * HS + r / WS) * WDIM + ww * WS + r % WS;
            rsum[r] = 3.0f * g_sgate[b * LTOK + lr] / s;
        }
    }
    __syncthreads();

    // ---- Phase 3: O^T = V^T P^T ----
    {
        const int nbb = wid * 16;
        float acc[2][2][4] = {};
#pragma unroll
        for (int ks = 0; ks < 16; ks++) {
            const int kr = ks * 8;
            uint32_t af[2][4];
#pragma unroll
            for (int mt = 0; mt < 2; mt++) {
                const int mr = mt * 16;
                af[mt][0] = Vs[(kr + tig    ) * 40 + mr + gid];
                af[mt][1] = Vs[(kr + tig    ) * 40 + mr + gid + 8];
                af[mt][2] = Vs[(kr + tig + 4) * 40 + mr + gid];
                af[mt][3] = Vs[(kr + tig + 4) * 40 + mr + gid + 8];
            }
            uint32_t bf[2][2];
#pragma unroll
            for (int nt = 0; nt < 2; nt++) {
                const int nb = nbb + nt * 8;
                bf[nt][0] = Su[(nb + gid) * 132 + kr + tig];
                bf[nt][1] = Su[(nb + gid) * 132 + kr + tig + 4];
            }
#pragma unroll
            for (int mt = 0; mt < 2; mt++)
#pragma unroll
                for (int nt = 0; nt < 2; nt++)
                    mma_tf32(acc[mt][nt], af[mt], bf[nt]);
        }
        __syncthreads();

#pragma unroll
        for (int mt = 0; mt < 2; mt++) {
            const int dim0 = mt * 16 + gid;
#pragma unroll
            for (int nt = 0; nt < 2; nt++) {
                const int r = nbb + nt * 8 + tig * 2;
                const float s0 = rsum[r], s1 = rsum[r + 1];
                Os[r * 33 + dim0]           = acc[mt][nt][0] * s0;
                Os[(r + 1) * 33 + dim0]     = acc[mt][nt][1] * s1;
                Os[r * 33 + dim0 + 8]       = acc[mt][nt][2] * s0;
                Os[(r + 1) * 33 + dim0 + 8] = acc[mt][nt][3] * s1;
            }
        }
    }
    __syncthreads();

    // ---- Phase 4: transposed NCHW writeout ----
#pragma unroll
    for (int cc = 0; cc < 4; cc++) {
        const int c = wid * 4 + cc;
        float* cbase = g_fuimg + ((size_t)b * CCH + co + c) * LTOK;
#pragma unroll
        for (int rp = 0; rp < 4; rp++) {
            const int ts = rp * 32 + lane;
            const int l  = (wh * HS + ts / WS) * WDIM + ww * WS + ts % WS;
            cbase[l] = Os[ts * 33 + c];
        }
    }
}

__global__ __launch_bounds__(256) void attn_both_kernel()
{
    const int bid = blockIdx.x;
    if (bid < ATT_BLOCKS) attn_body<8, 16, 0>(bid);
    else                  attn_body<16, 8, 96>(bid - ATT_BLOCKS);
}

// ---------------------------------------------------------------------------
// zero g_pool
// ---------------------------------------------------------------------------
__global__ void zero_pool_kernel()
{
    const int i = blockIdx.x * 256 + threadIdx.x;
    if (i < BSZ * CCH) g_pool[i] = 0.0f;
}

// ---------------------------------------------------------------------------
// Depthwise 3x3 + bias + BN + GELU, 4 px/thread (proven).
// WHICH 0 accumulates per-(b,c) sum into g_pool.
// ---------------------------------------------------------------------------
template<int WHICH>
__global__ __launch_bounds__(256) void dwconv_bn_gelu_kernel(
    const float* __restrict__ xin,
    const float* __restrict__ wdw,
    const float* __restrict__ bdw,
    const float* __restrict__ gbn,
    const float* __restrict__ bebn)
{
    const int idx = blockIdx.x * 256 + threadIdx.x;
    const int w0 = (idx & 31) * 4;
    const int h  = (idx >> 5) & 127;
    const int bc = idx >> 12;
    const int c  = bc % CCH;

    const float* in  = (WHICH == 0) ? xin : g_fuimg;
    float*       out = (WHICH == 0) ? g_conv1 : g_conv2;

    const float* p = in + (size_t)bc * LTOK;
    float wk[9];
#pragma unroll
    for (int i = 0; i < 9; i++) wk[i] = wdw[c * 9 + i];

    float o0 = 0.f, o1 = 0.f, o2 = 0.f, o3 = 0.f;
#pragma unroll
    for (int r = 0; r < 3; r++) {
        const int hh = h - 1 + r;
        if (hh < 0 || hh >= HDIM) continue;
        const float* row = p + hh * WDIM;
        const float4 cc = *(const float4*)(row + w0);
        const float lf = (w0 > 0)   ? row[w0 - 1] : 0.0f;
        const float rt = (w0 < 124) ? row[w0 + 4] : 0.0f;
        const float k0 = wk[r*3+0], k1 = wk[r*3+1], k2 = wk[r*3+2];
        o0 = fmaf(k0, lf,   fmaf(k1, cc.x, fmaf(k2, cc.y, o0)));
        o1 = fmaf(k0, cc.x, fmaf(k1, cc.y, fmaf(k2, cc.z, o1)));
        o2 = fmaf(k0, cc.y, fmaf(k1, cc.z, fmaf(k2, cc.w, o2)));
        o3 = fmaf(k0, cc.z, fmaf(k1, cc.w, fmaf(k2, rt,   o3)));
    }
    const float bni = rsqrtf(1.0f + 1e-5f);
    const float sc = gbn[c] * bni, bb = bebn[c], bs = bdw[c];
    float4 o;
    o.x = gelu_erf((o0 + bs) * sc + bb);
    o.y = gelu_erf((o1 + bs) * sc + bb);
    o.z = gelu_erf((o2 + bs) * sc + bb);
    o.w = gelu_erf((o3 + bs) * sc + bb);
    *(float4*)(out + (size_t)idx * 4) = o;

    if (WHICH == 0) {
        float s = o.x + o.y + o.z + o.w;
#pragma unroll
        for (int off = 16; off > 0; off >>= 1)
            s += __shfl_xor_sync(0xffffffffu, s, off);
        __shared__ float red[8];
        if ((threadIdx.x & 31) == 0) red[threadIdx.x >> 5] = s;
        __syncthreads();
        if (threadIdx.x == 0) {
            float tot = 0.0f;
#pragma unroll
            for (int i = 0; i < 8; i++) tot += red[i];
            atomicAdd(&g_pool[bc], tot);
        }
    }
}

// ---------------------------------------------------------------------------
// Spatial interaction -> g_sgate (R11-proven)
// ---------------------------------------------------------------------------
__global__ __launch_bounds__(256) void spatial_kernel(
    const float* __restrict__ w_si1, const float* __restrict__ b_si1,
    const float* __restrict__ g_si,  const float* __restrict__ be_si,
    const float* __restrict__ w_si2, const float* __restrict__ b_si2)
{
    __shared__ float wsm[CCH * C8];
    for (int i = threadIdx.x; i < CCH * C8; i += 256)
        wsm[i] = w_si1[(i % C8) * CCH + (i / C8)];
    __syncthreads();

    const int pid = (blockIdx.x * 256 + threadIdx.x) * 2;
    const int b  = pid / LTOK;
    const int hw = pid % LTOK;

    float t0[C8], t1[C8];
#pragma unroll
    for (int o = 0; o < C8; o++) { t0[o] = 0.0f; t1[o] = 0.0f; }

    const float* base = g_conv1 + (size_t)b * CCH * LTOK + hw;
#pragma unroll 4
    for (int c = 0; c < CCH; c++) {
        const float2 v = *(const float2*)(base + (size_t)c * LTOK);
        const float4* wr = (const float4*)&wsm[c * C8];
#pragma unroll
        for (int o4 = 0; o4 < 6; o4++) {
            const float4 w = wr[o4];
            t0[o4*4+0] = fmaf(w.x, v.x, t0[o4*4+0]);
            t0[o4*4+1] = fmaf(w.y, v.x, t0[o4*4+1]);
            t0[o4*4+2] = fmaf(w.z, v.x, t0[o4*4+2]);
            t0[o4*4+3] = fmaf(w.w, v.x, t0[o4*4+3]);
            t1[o4*4+0] = fmaf(w.x, v.y, t1[o4*4+0]);
            t1[o4*4+1] = fmaf(w.y, v.y, t1[o4*4+1]);
            t1[o4*4+2] = fmaf(w.z, v.y, t1[o4*4+2]);
            t1[o4*4+3] = fmaf(w.w, v.y, t1[o4*4+3]);
        }
    }

    const float bni = rsqrtf(1.0f + 1e-5f);
    float s0 = b_si2[0], s1 = s0;
#pragma unroll
    for (int o = 0; o < C8; o++) {
        const float gb = g_si[o] * bni, be = be_si[o], bi = b_si1[o], w2 = w_si2[o];
        s0 = fmaf(w2, gelu_erf((t0[o] + bi) * gb + be), s0);
        s1 = fmaf(w2, gelu_erf((t1[o] + bi) * gb + be), s1);
    }
    g_sgate[pid]     = 1.0f + sigmoidf_(s0);
    g_sgate[pid + 1] = 1.0f + sigmoidf_(s1);
}

// ---------------------------------------------------------------------------
// Channel interaction -> g_cgate (g_pool holds SUM; scale by 1/LTOK)
// ---------------------------------------------------------------------------
__global__ __launch_bounds__(192) void channel_kernel(
    const float* __restrict__ w_ci1, const float* __restrict__ b_ci1,
    const float* __restrict__ g_ci,  const float* __restrict__ be_ci,
    const float* __restrict__ w_ci2, const float* __restrict__ b_ci2)
{
    const int b = blockIdx.x;
    __shared__ float t[C8];
    const float bni = rsqrtf(1.0f + 1e-5f);
    const float inv = 1.0f / LTOK;
    if (threadIdx.x < C8) {
        const int o = threadIdx.x;
        float s = b_ci1[o];
        for (int c = 0; c < CCH; c++)
            s = fmaf(w_ci1[o * CCH + c], g_pool[b * CCH + c] * inv, s);
        s = s * (g_ci[o] * bni) + be_ci[o];
        t[o] = gelu_erf(s);
    }
    __syncthreads();
    const int c = threadIdx.x;
    float s = b_ci2[c];
#pragma unroll
    for (int o = 0; o < C8; o++) s = fmaf(w_ci2[c * C8 + o], t[o], s);
    g_cgate[b * CCH + c] = 1.0f + sigmoidf_(s);
}

// ---------------------------------------------------------------------------
// kernel_launch (R14 structure: single stream, merged attention)
// ---------------------------------------------------------------------------
extern "C" void kernel_launch(void* const* d_in, const int* in_sizes, int n_in,
                              void* d_out, int out_size)
{
    const float* x      = (const float*)d_in[0];
    const float* w_qkv  = (const float*)d_in[1];
    const float* b_qkv  = (const float*)d_in[2];
    const float* w_dw1  = (const float*)d_in[3];
    const float* b_dw1  = (const float*)d_in[4];
    const float* gbn1   = (const float*)d_in[5];
    const float* bebn1  = (const float*)d_in[6];
    const float* w_si1  = (const float*)d_in[7];
    const float* b_si1  = (const float*)d_in[8];
    const float* g_si   = (const float*)d_in[9];
    const float* be_si  = (const float*)d_in[10];
    const float* w_si2  = (const float*)d_in[11];
    const float* b_si2  = (const float*)d_in[12];
    const float* w_ci1  = (const float*)d_in[13];
    const float* b_ci1  = (const float*)d_in[14];
    const float* g_ci   = (const float*)d_in[15];
    const float* be_ci  = (const float*)d_in[16];
    const float* w_ci2  = (const float*)d_in[17];
    const float* b_ci2  = (const float*)d_in[18];
    const float* w_dw2  = (const float*)d_in[19];
    const float* b_dw2  = (const float*)d_in[20];
    const float* gbn2   = (const float*)d_in[21];
    const float* bebn2  = (const float*)d_in[22];
    const float* w_proj = (const float*)d_in[23];
    const float* b_proj = (const float*)d_in[24];
    float* out = (float*)d_out;

    cudaFuncSetAttribute(attn_both_kernel,
                         cudaFuncAttributeMaxDynamicSharedMemorySize, ATT_SMEM);

    // 0) qkv = x @ w_qkv + b_qkv  (double-buffered, fp16 output)
    mma_gemm_kernel<0, 3 * CCH><<<dim3((3 * CCH) / 96, MTOT / 128), 192>>>(
        x, w_qkv, b_qkv, nullptr);

    // 1) conv path (mean fused into dwconv<0>)
    zero_pool_kernel<<<(BSZ * CCH + 255) / 256, 256>>>();
    dwconv_bn_gelu_kernel<0><<<(MTOT * CCH) / 1024, 256>>>(x, w_dw1, b_dw1, gbn1, bebn1);
    spatial_kernel<<<MTOT / 512, 256>>>(w_si1, b_si1, g_si, be_si, w_si2, b_si2);
    channel_kernel<<<BSZ, CCH>>>(w_ci1, b_ci1, g_ci, be_ci, w_ci2, b_ci2);

    // 2) attention — both variants in one grid (gate + transpose fused)
    attn_both_kernel<<<2 * ATT_BLOCKS, 256, ATT_SMEM>>>();

    // 3) conv2 -> g_conv2
    dwconv_bn_gelu_kernel<1><<<(MTOT * CCH) / 1024, 256>>>(nullptr, w_dw2, b_dw2, gbn2, bebn2);

    // 4) out = (channel-gated conv2) @ w_proj + b_proj  (double-buffered)
    mma_gemm_kernel<1, CCH><<<dim3(CCH / 96, MTOT / 128), 192>>>(
        nullptr, w_proj, b_proj, out);
}